// round 9
// baseline (speedup 1.0000x reference)
#include <cuda_runtime.h>
#include <cuda_fp16.h>
#include <math.h>

#define B_   8
#define H_   64
#define W_   64
#define M_   32768
#define C_   192
#define QKVC 576
#define HD   64
#define GN   768   // G row stride: 576 (Gk/Gv) + 162 (OffG) + pad

// ---------------------------------------------------------------------------
// Scratch (static device globals) — fp16 end-to-end intermediates
// ---------------------------------------------------------------------------
__device__ __half g_qkv[M_ * QKVC];      // [pos][576]
__device__ __half g_G[4][M_ * GN];       // z = {k2, v2, k3, v3}
__device__ __half g_dk2[M_ * HD];
__device__ __half g_dv2[M_ * HD];
__device__ __half g_dk3[M_ * HD];
__device__ __half g_dv3[M_ * HD];
__device__ __half g_attn[M_ * C_];       // [pos][branch*64+c]
__device__ __half g_Wc[2][GN * HD];      // combined [def | off] weights per branch

// ---------------------------------------------------------------------------
// fp16 MMA helpers
// ---------------------------------------------------------------------------
__device__ __forceinline__ void mma_f16(float (&d)[4], const unsigned (&a)[4],
                                        const unsigned b0, const unsigned b1) {
    asm volatile(
        "mma.sync.aligned.m16n8k16.row.col.f32.f16.f16.f32 "
        "{%0,%1,%2,%3}, {%4,%5,%6,%7}, {%8,%9}, {%0,%1,%2,%3};\n"
        : "+f"(d[0]), "+f"(d[1]), "+f"(d[2]), "+f"(d[3])
        : "r"(a[0]), "r"(a[1]), "r"(a[2]), "r"(a[3]), "r"(b0), "r"(b1));
}

__device__ __forceinline__ void ldsm4(unsigned (&r)[4], unsigned addr) {
    asm volatile("ldmatrix.sync.aligned.m8n8.x4.shared.b16 {%0,%1,%2,%3}, [%4];"
                 : "=r"(r[0]), "=r"(r[1]), "=r"(r[2]), "=r"(r[3]) : "r"(addr));
}

__device__ __forceinline__ uint2 pack_h4(float4 f) {
    __half2 h01 = __float22half2_rn(make_float2(f.x, f.y));
    __half2 h23 = __float22half2_rn(make_float2(f.z, f.w));
    uint2 v;
    v.x = *reinterpret_cast<unsigned*>(&h01);
    v.y = *reinterpret_cast<unsigned*>(&h23);
    return v;
}

template<typename T> struct RawVec;
template<> struct RawVec<float> {
    float4 v;
    __device__ __forceinline__ void load(const float* p) { v = *reinterpret_cast<const float4*>(p); }
    __device__ __forceinline__ uint2 pack() const { return pack_h4(v); }
};
template<> struct RawVec<__half> {
    uint2 v;
    __device__ __forceinline__ void load(const __half* p) { v = *reinterpret_cast<const uint2*>(p); }
    __device__ __forceinline__ uint2 pack() const { return v; }
};

// ---------------------------------------------------------------------------
// fp16 NT GEMM core. Block 128x64, 4 warps (2x2), warp tile 64x32, BK=16,
// double-buffered, ldmatrix fragments. PADW=12 words keeps ldmatrix rows on
// distinct bank groups.
// ---------------------------------------------------------------------------
#define BM 128
#define BN 64
#define PADW 12
#define ABUFW (BM * PADW)
#define BBUFW (BN * PADW)

template<typename TA, typename TB, bool HOUT>
__device__ __forceinline__ void gemm16(
    const TA* __restrict__ A, int lda,
    const TB* __restrict__ Wt, int ldb,
    const float* __restrict__ bias, void* __restrict__ Cp, int ldc,
    int m0, int n0, int Kd, unsigned* As, unsigned* Bs)
{
    const int tid  = threadIdx.x;
    const int lane = tid & 31;
    const int warp = tid >> 5;
    const int wm = warp >> 1, wn = warp & 1;
    const int g = lane >> 2, t = lane & 3;
    const int lrow = tid >> 2, lkq = tid & 3;

    unsigned a_base = (unsigned)__cvta_generic_to_shared(As);
    unsigned b_base = (unsigned)__cvta_generic_to_shared(Bs);
    unsigned aaddr[4], baddr[2];
    {
        int mrow = ((lane >> 3) & 1) * 8 + (lane & 7);
        int ah = (lane >> 4);
        #pragma unroll
        for (int mi = 0; mi < 4; mi++)
            aaddr[mi] = a_base + ((wm * 64 + mi * 16 + mrow) * PADW + ah * 4) * 4u;
        int bh = (lane >> 3) & 1;
        int brow0 = ((lane >> 4) & 1) * 8 + (lane & 7);
        #pragma unroll
        for (int np = 0; np < 2; np++)
            baddr[np] = b_base + ((wn * 32 + np * 16 + brow0) * PADW + bh * 4) * 4u;
    }

    float acc[4][4][4] = {};
    const int nit = Kd >> 4;
    RawVec<TA> ra[4];
    RawVec<TB> rb[2];

    #pragma unroll
    for (int i = 0; i < 4; i++)
        ra[i].load(&A[(size_t)(m0 + lrow + 32 * i) * lda + lkq * 4]);
    #pragma unroll
    for (int i = 0; i < 2; i++)
        rb[i].load(&Wt[(size_t)(n0 + lrow + 32 * i) * ldb + lkq * 4]);
    #pragma unroll
    for (int i = 0; i < 4; i++)
        *reinterpret_cast<uint2*>(&As[(lrow + 32 * i) * PADW + lkq * 2]) = ra[i].pack();
    #pragma unroll
    for (int i = 0; i < 2; i++)
        *reinterpret_cast<uint2*>(&Bs[(lrow + 32 * i) * PADW + lkq * 2]) = rb[i].pack();
    __syncthreads();

    for (int it = 0; it < nit; it++) {
        const int buf = it & 1;
        const bool more = (it + 1) < nit;
        const unsigned abytes = buf * (ABUFW * 4);
        const unsigned bbytes = buf * (BBUFW * 4);

        if (more) {
            int k0 = (it + 1) << 4;
            #pragma unroll
            for (int i = 0; i < 4; i++)
                ra[i].load(&A[(size_t)(m0 + lrow + 32 * i) * lda + k0 + lkq * 4]);
            #pragma unroll
            for (int i = 0; i < 2; i++)
                rb[i].load(&Wt[(size_t)(n0 + lrow + 32 * i) * ldb + k0 + lkq * 4]);
        }

        unsigned af[4][4], bf[2][4];
        #pragma unroll
        for (int mi = 0; mi < 4; mi++) ldsm4(af[mi], aaddr[mi] + abytes);
        #pragma unroll
        for (int np = 0; np < 2; np++) ldsm4(bf[np], baddr[np] + bbytes);

        #pragma unroll
        for (int mi = 0; mi < 4; mi++)
            #pragma unroll
            for (int nj = 0; nj < 4; nj++)
                mma_f16(acc[mi][nj], af[mi], bf[nj >> 1][(nj & 1) * 2], bf[nj >> 1][(nj & 1) * 2 + 1]);

        if (more) {
            const int nb = (it + 1) & 1;
            #pragma unroll
            for (int i = 0; i < 4; i++)
                *reinterpret_cast<uint2*>(&As[nb * ABUFW + (lrow + 32 * i) * PADW + lkq * 2]) = ra[i].pack();
            #pragma unroll
            for (int i = 0; i < 2; i++)
                *reinterpret_cast<uint2*>(&Bs[nb * BBUFW + (lrow + 32 * i) * PADW + lkq * 2]) = rb[i].pack();
            __syncthreads();
        }
    }

    #pragma unroll
    for (int mi = 0; mi < 4; mi++) {
        int r = m0 + wm * 64 + mi * 16 + g;
        #pragma unroll
        for (int nj = 0; nj < 4; nj++) {
            int c = n0 + wn * 32 + nj * 8 + 2 * t;
            float b0 = bias ? bias[c] : 0.f;
            float b1 = bias ? bias[c + 1] : 0.f;
            float v0 = acc[mi][nj][0] + b0, v1 = acc[mi][nj][1] + b1;
            float v2 = acc[mi][nj][2] + b0, v3 = acc[mi][nj][3] + b1;
            if (HOUT) {
                __half* Ch = (__half*)Cp;
                *reinterpret_cast<__half2*>(&Ch[(size_t)r * ldc + c]) =
                    __float22half2_rn(make_float2(v0, v1));
                *reinterpret_cast<__half2*>(&Ch[(size_t)(r + 8) * ldc + c]) =
                    __float22half2_rn(make_float2(v2, v3));
            } else {
                float* Cf = (float*)Cp;
                *reinterpret_cast<float2*>(&Cf[(size_t)r * ldc + c]) = make_float2(v0, v1);
                *reinterpret_cast<float2*>(&Cf[(size_t)(r + 8) * ldc + c]) = make_float2(v2, v3);
            }
        }
    }
}

// qkv = x @ qkv_w^T  (fp32 in, fp16 out)
__global__ __launch_bounds__(128) void mma_qkv(
    const float* __restrict__ x, const float* __restrict__ w,
    __half* __restrict__ C)
{
    __shared__ __align__(16) unsigned As[2 * ABUFW];
    __shared__ __align__(16) unsigned Bs[2 * BBUFW];
    gemm16<float, float, true>(x, C_, w, C_, nullptr, C, QKVC,
                               blockIdx.y * BM, blockIdx.x * BN, C_, As, Bs);
}

// G GEMMs for one branch: z = zbase + blockIdx.z, z in {k, v}.
__global__ __launch_bounds__(128) void mma_g(
    const __half* __restrict__ qkv, const __half* __restrict__ Wc,
    __half* __restrict__ G, int zbase)
{
    const int z = zbase + blockIdx.z;
    const int n0 = blockIdx.x * BN;
    if ((z & 1) && n0 >= QKVC) return;
    __shared__ __align__(16) unsigned As[2 * ABUFW];
    __shared__ __align__(16) unsigned Bs[2 * BBUFW];
    const int ofsA = 256 + (z >> 1) * 64 + (z & 1) * 192;
    gemm16<__half, __half, true>(qkv + ofsA, QKVC, Wc + (size_t)(z >> 1) * GN * HD, HD,
                                 nullptr, G + (size_t)z * M_ * GN, GN,
                                 blockIdx.y * BM, n0, HD, As, Bs);
}

// out = attn @ proj_w^T + proj_b  (fp16 A, fp32 W, fp32 out)
__global__ __launch_bounds__(128) void mma_proj(
    const __half* __restrict__ A, const float* __restrict__ w,
    const float* __restrict__ bias, float* __restrict__ out)
{
    __shared__ __align__(16) unsigned As[2 * ABUFW];
    __shared__ __align__(16) unsigned Bs[2 * BBUFW];
    gemm16<__half, float, false>(A, C_, w, C_, bias, out, C_,
                                 blockIdx.y * BM, blockIdx.x * BN, C_, As, Bs);
}

// ---------------------------------------------------------------------------
// Build combined weights (fp16)
// ---------------------------------------------------------------------------
__global__ void build_w(const float* __restrict__ dw2, const float* __restrict__ ow2,
                        const float* __restrict__ dw3, const float* __restrict__ ow3,
                        __half* __restrict__ Wc)
{
    int i = blockIdx.x * blockDim.x + threadIdx.x;
    if (i >= 2 * GN * HD) return;
    int br = i / (GN * HD);
    int r  = (i / HD) % GN;
    int c  = i % HD;
    const float* dw = br ? dw3 : dw2;
    const float* ow = br ? ow3 : ow2;
    float v = 0.f;
    if (r < QKVC) {
        int kk = r >> 6, o = r & 63;
        v = dw[o * 576 + c * 9 + kk];
    } else if (r < QKVC + 162) {
        int rr = r - QKVC, kk = rr / 18, o = rr % 18;
        v = ow[o * 576 + c * 9 + kk];
    }
    Wc[i] = __float2half(v);
}

// ---------------------------------------------------------------------------
// Deformable gather for ONE branch (launched right after that branch's G is
// written so G reads hit L2). One warp per position.
// ---------------------------------------------------------------------------
__global__ __launch_bounds__(256) void deform_gather(
    const __half* __restrict__ G, int br,
    const float* __restrict__ offb, const float* __restrict__ defb,
    __half* __restrict__ dk, __half* __restrict__ dv)
{
    const int dil = br + 2;
    const __half* __restrict__ Gk = G + (size_t)(2 * br) * M_ * GN;
    const __half* __restrict__ Gv = G + (size_t)(2 * br + 1) * M_ * GN;

    const int warp = threadIdx.x >> 5, lane = threadIdx.x & 31;
    const int pos = (blockIdx.x << 3) + warp;
    const int b = pos >> 12, hw = pos & 4095, h = hw >> 6, x = hw & 63;
    const int rbase = b << 12;

    // Phase 1: offsets (18 channels on lanes 0..17)
    float offa = (lane < 18) ? offb[lane] : 0.f;
    #pragma unroll
    for (int kq = 0; kq < 9; kq++) {
        int y  = h + (kq / 3 - 1) * dil;
        int xx = x + (kq % 3 - 1) * dil;
        if (lane < 18 && y >= 0 && y < H_ && xx >= 0 && xx < W_)
            offa += __half2float(Gk[(size_t)(rbase + (y << 6) + xx) * GN + QKVC + kq * 18 + lane]);
    }

    // Phase 2: per-tap bilinear setup (lanes 0..8 meaningful)
    int kk = lane;
    float offy = __shfl_sync(0xffffffffu, offa, (2 * lane) & 31);
    float offx = __shfl_sync(0xffffffffu, offa, (2 * lane + 1) & 31);
    float py = (float)h + (float)((kk / 3) * dil - dil) + offy;
    float px = (float)x + (float)((kk % 3) * dil - dil) + offx;
    float y0f = floorf(py), x0f = floorf(px);
    float wy = py - y0f, wx = px - x0f;
    int y0 = (int)y0f, x0 = (int)x0f, y1 = y0 + 1, x1 = x0 + 1;
    float fy0 = (float)(y0 >= 0 && y0 < H_);
    float fy1 = (float)(y1 >= 0 && y1 < H_);
    float fx0 = (float)(x0 >= 0 && x0 < W_);
    float fx1 = (float)(x1 >= 0 && x1 < W_);
    float w00 = (1.f - wy) * (1.f - wx) * fy0 * fx0;
    float w01 = (1.f - wy) * wx        * fy0 * fx1;
    float w10 = wy * (1.f - wx)        * fy1 * fx0;
    float w11 = wy * wx                * fy1 * fx1;
    int y0c = min(max(y0, 0), H_ - 1), y1c = min(max(y1, 0), H_ - 1);
    int x0c = min(max(x0, 0), W_ - 1), x1c = min(max(x1, 0), W_ - 1);
    int tapofs = kk * 64;
    int i00 = (rbase + (y0c << 6) + x0c) * GN + tapofs;
    int i01 = (rbase + (y0c << 6) + x1c) * GN + tapofs;
    int i10 = (rbase + (y1c << 6) + x0c) * GN + tapofs;
    int i11 = (rbase + (y1c << 6) + x1c) * GN + tapofs;

    const int arr = lane >> 4;            // 0 = k, 1 = v
    const int c4 = (lane & 15) * 4;
    const __half* __restrict__ Gs = arr ? Gv : Gk;

    float4 acc = *reinterpret_cast<const float4*>(&defb[c4]);

    #pragma unroll
    for (int tp = 0; tp < 9; tp++) {
        float a00 = __shfl_sync(0xffffffffu, w00, tp);
        float a01 = __shfl_sync(0xffffffffu, w01, tp);
        float a10 = __shfl_sync(0xffffffffu, w10, tp);
        float a11 = __shfl_sync(0xffffffffu, w11, tp);
        int   j00 = __shfl_sync(0xffffffffu, i00, tp);
        int   j01 = __shfl_sync(0xffffffffu, i01, tp);
        int   j10 = __shfl_sync(0xffffffffu, i10, tp);
        int   j11 = __shfl_sync(0xffffffffu, i11, tp);
        uint2 raw;
        __half2 p0, p1;
        raw = *reinterpret_cast<const uint2*>(&Gs[j00 + c4]);
        p0 = *reinterpret_cast<__half2*>(&raw.x); p1 = *reinterpret_cast<__half2*>(&raw.y);
        { float2 lo = __half22float2(p0), hi = __half22float2(p1);
          acc.x += a00 * lo.x; acc.y += a00 * lo.y; acc.z += a00 * hi.x; acc.w += a00 * hi.y; }
        raw = *reinterpret_cast<const uint2*>(&Gs[j01 + c4]);
        p0 = *reinterpret_cast<__half2*>(&raw.x); p1 = *reinterpret_cast<__half2*>(&raw.y);
        { float2 lo = __half22float2(p0), hi = __half22float2(p1);
          acc.x += a01 * lo.x; acc.y += a01 * lo.y; acc.z += a01 * hi.x; acc.w += a01 * hi.y; }
        raw = *reinterpret_cast<const uint2*>(&Gs[j10 + c4]);
        p0 = *reinterpret_cast<__half2*>(&raw.x); p1 = *reinterpret_cast<__half2*>(&raw.y);
        { float2 lo = __half22float2(p0), hi = __half22float2(p1);
          acc.x += a10 * lo.x; acc.y += a10 * lo.y; acc.z += a10 * hi.x; acc.w += a10 * hi.y; }
        raw = *reinterpret_cast<const uint2*>(&Gs[j11 + c4]);
        p0 = *reinterpret_cast<__half2*>(&raw.x); p1 = *reinterpret_cast<__half2*>(&raw.y);
        { float2 lo = __half22float2(p0), hi = __half22float2(p1);
          acc.x += a11 * lo.x; acc.y += a11 * lo.y; acc.z += a11 * hi.x; acc.w += a11 * hi.y; }
    }

    uint2 st;
    __half2 s01 = __float22half2_rn(make_float2(acc.x, acc.y));
    __half2 s23 = __float22half2_rn(make_float2(acc.z, acc.w));
    st.x = *reinterpret_cast<unsigned*>(&s01);
    st.y = *reinterpret_cast<unsigned*>(&s23);
    __half* __restrict__ dst = arr ? dv : dk;
    *reinterpret_cast<uint2*>(&dst[pos * HD + c4]) = st;
}

// ---------------------------------------------------------------------------
// 9-tap local attention, all 3 branches (blockIdx.y). Warp per position.
// Lane holds channels (2*lane, 2*lane+1).
// ---------------------------------------------------------------------------
__global__ __launch_bounds__(256) void attn_all(
    const __half* __restrict__ qkv,
    const __half* __restrict__ dk2, const __half* __restrict__ dv2,
    const __half* __restrict__ dk3, const __half* __restrict__ dv3,
    __half* __restrict__ ob)
{
    const int br = blockIdx.y;
    const int warp = threadIdx.x >> 5, lane = threadIdx.x & 31;
    const int pos = (blockIdx.x << 3) + warp;
    const int b = pos >> 12, hw = pos & 4095, h = hw >> 6, x = hw & 63;

    const __half* kb; const __half* vb; int kstride, kofs, vofs, dil;
    if (br == 0)      { kb = qkv; vb = qkv; kstride = QKVC; kofs = 192; vofs = 384; dil = 1; }
    else if (br == 1) { kb = dk2; vb = dv2; kstride = HD;   kofs = 0;   vofs = 0;   dil = 2; }
    else              { kb = dk3; vb = dv3; kstride = HD;   kofs = 0;   vofs = 0;   dil = 3; }

    const int qofs = br * 64;
    float2 q = __half22float2(*reinterpret_cast<const __half2*>(&qkv[pos * QKVC + qofs + 2 * lane]));

    float logits[9];
    #pragma unroll
    for (int kk = 0; kk < 9; kk++) {
        int y = h + (kk / 3 - 1) * dil;
        int xx = x + (kk % 3 - 1) * dil;
        float p = 0.f;
        if (y >= 0 && y < H_ && xx >= 0 && xx < W_) {
            const __half* kp = kb + ((b << 12) + (y << 6) + xx) * kstride + kofs;
            float2 kv = __half22float2(*reinterpret_cast<const __half2*>(&kp[2 * lane]));
            p = q.x * kv.x + q.y * kv.y;
        }
        #pragma unroll
        for (int s = 16; s; s >>= 1) p += __shfl_xor_sync(0xffffffffu, p, s);
        logits[kk] = p * 0.125f;
    }

    float mx = logits[0];
    #pragma unroll
    for (int kk = 1; kk < 9; kk++) mx = fmaxf(mx, logits[kk]);
    float e[9], den = 0.f;
    #pragma unroll
    for (int kk = 0; kk < 9; kk++) { e[kk] = __expf(logits[kk] - mx); den += e[kk]; }
    float inv = 1.f / den;

    float o0 = 0.f, o1 = 0.f;
    #pragma unroll
    for (int kk = 0; kk < 9; kk++) {
        int y = h + (kk / 3 - 1) * dil;
        int xx = x + (kk % 3 - 1) * dil;
        if (y >= 0 && y < H_ && xx >= 0 && xx < W_) {
            const __half* vp = vb + ((b << 12) + (y << 6) + xx) * kstride + vofs;
            float2 vv = __half22float2(*reinterpret_cast<const __half2*>(&vp[2 * lane]));
            float a = e[kk] * inv;
            o0 += a * vv.x;
            o1 += a * vv.y;
        }
    }
    *reinterpret_cast<__half2*>(&ob[pos * C_ + qofs + 2 * lane]) =
        __float22half2_rn(make_float2(o0, o1));
}

// ---------------------------------------------------------------------------
// Launch: per-branch mma_g -> gather interleaving for L2 residency of G.
// ---------------------------------------------------------------------------
extern "C" void kernel_launch(void* const* d_in, const int* in_sizes, int n_in,
                              void* d_out, int out_size)
{
    const float* x      = (const float*)d_in[0];
    const float* qkv_w  = (const float*)d_in[1];
    const float* proj_w = (const float*)d_in[2];
    const float* proj_b = (const float*)d_in[3];
    const float* off_w2 = (const float*)d_in[4];
    const float* off_b2 = (const float*)d_in[5];
    const float* def_w2 = (const float*)d_in[6];
    const float* def_b2 = (const float*)d_in[7];
    const float* off_w3 = (const float*)d_in[8];
    const float* off_b3 = (const float*)d_in[9];
    const float* def_w3 = (const float*)d_in[10];
    const float* def_b3 = (const float*)d_in[11];
    float* out = (float*)d_out;

    __half *p_qkv, *p_G, *p_dk2, *p_dv2, *p_dk3, *p_dv3, *p_attn, *p_wc;
    cudaGetSymbolAddress((void**)&p_qkv,  g_qkv);
    cudaGetSymbolAddress((void**)&p_G,    g_G);
    cudaGetSymbolAddress((void**)&p_dk2,  g_dk2);
    cudaGetSymbolAddress((void**)&p_dv2,  g_dv2);
    cudaGetSymbolAddress((void**)&p_dk3,  g_dk3);
    cudaGetSymbolAddress((void**)&p_dv3,  g_dv3);
    cudaGetSymbolAddress((void**)&p_attn, g_attn);
    cudaGetSymbolAddress((void**)&p_wc,   g_Wc);

    // 0) combined deform/offset weights (fp16)
    build_w<<<(2 * GN * HD + 255) / 256, 256>>>(def_w2, off_w2, def_w3, off_w3, p_wc);

    // 1) qkv = x @ qkv_w^T  -> fp16
    mma_qkv<<<dim3(QKVC / BN, M_ / BM), 128>>>(x, qkv_w, p_qkv);

    // 2) branch 0 (dil=2): G then gather while G is L2-resident
    mma_g<<<dim3(GN / BN, M_ / BM, 2), 128>>>(p_qkv, p_wc, p_G, 0);
    deform_gather<<<M_ / 8, 256>>>(p_G, 0, off_b2, def_b2, p_dk2, p_dv2);

    // 3) branch 1 (dil=3)
    mma_g<<<dim3(GN / BN, M_ / BM, 2), 128>>>(p_qkv, p_wc, p_G, 2);
    deform_gather<<<M_ / 8, 256>>>(p_G, 1, off_b3, def_b3, p_dk3, p_dv3);

    // 4) attention, all branches -> fp16 attn
    attn_all<<<dim3(M_ / 8, 3), 256>>>(p_qkv, p_dk2, p_dv2, p_dk3, p_dv3, p_attn);

    // 5) out = attn @ proj_w^T + proj_b  (fp32 out)
    mma_proj<<<dim3(C_ / BN, M_ / BM), 128>>>(p_attn, proj_w, proj_b, out);
}

// round 12
// speedup vs baseline: 1.0530x; 1.0530x over previous
#include <cuda_runtime.h>
#include <cuda_fp16.h>
#include <math.h>

#define B_   8
#define H_   64
#define W_   64
#define M_   32768
#define C_   192
#define QKVC 576
#define HD   64
#define GN   768   // G row stride: 576 (Gk/Gv) + 162 (OffG) + pad

// ---------------------------------------------------------------------------
// Scratch (static device globals) — fp16 end-to-end intermediates
// ---------------------------------------------------------------------------
__device__ __half g_qkv[M_ * QKVC];      // [pos][576]
__device__ __half g_G[4][M_ * GN];       // z = {k2, v2, k3, v3}
__device__ __half g_dk2[M_ * HD];
__device__ __half g_dv2[M_ * HD];
__device__ __half g_dk3[M_ * HD];
__device__ __half g_dv3[M_ * HD];
__device__ __half g_attn[M_ * C_];       // [pos][branch*64+c]
__device__ __half g_Wc[2][GN * HD];      // combined [def | off] weights per branch

// ---------------------------------------------------------------------------
// fp16 MMA helpers
// ---------------------------------------------------------------------------
__device__ __forceinline__ void mma_f16(float (&d)[4], const unsigned (&a)[4],
                                        const unsigned b0, const unsigned b1) {
    asm volatile(
        "mma.sync.aligned.m16n8k16.row.col.f32.f16.f16.f32 "
        "{%0,%1,%2,%3}, {%4,%5,%6,%7}, {%8,%9}, {%0,%1,%2,%3};\n"
        : "+f"(d[0]), "+f"(d[1]), "+f"(d[2]), "+f"(d[3])
        : "r"(a[0]), "r"(a[1]), "r"(a[2]), "r"(a[3]), "r"(b0), "r"(b1));
}

__device__ __forceinline__ void ldsm4(unsigned (&r)[4], unsigned addr) {
    asm volatile("ldmatrix.sync.aligned.m8n8.x4.shared.b16 {%0,%1,%2,%3}, [%4];"
                 : "=r"(r[0]), "=r"(r[1]), "=r"(r[2]), "=r"(r[3]) : "r"(addr));
}

__device__ __forceinline__ uint2 pack_h4(float4 f) {
    __half2 h01 = __float22half2_rn(make_float2(f.x, f.y));
    __half2 h23 = __float22half2_rn(make_float2(f.z, f.w));
    uint2 v;
    v.x = *reinterpret_cast<unsigned*>(&h01);
    v.y = *reinterpret_cast<unsigned*>(&h23);
    return v;
}

template<typename T> struct RawVec;
template<> struct RawVec<float> {
    float4 v;
    __device__ __forceinline__ void load(const float* p) { v = *reinterpret_cast<const float4*>(p); }
    __device__ __forceinline__ uint2 pack() const { return pack_h4(v); }
};
template<> struct RawVec<__half> {
    uint2 v;
    __device__ __forceinline__ void load(const __half* p) { v = *reinterpret_cast<const uint2*>(p); }
    __device__ __forceinline__ uint2 pack() const { return v; }
};

// ---------------------------------------------------------------------------
// fp16 NT GEMM core (generic K, double-buffered). Block 128x64, 4 warps,
// warp tile 64x32, BK=16, ldmatrix fragments. PADW=12 words keeps ldmatrix
// rows on distinct bank groups.
// ---------------------------------------------------------------------------
#define BM 128
#define BN 64
#define PADW 12
#define ABUFW (BM * PADW)
#define BBUFW (BN * PADW)

template<typename TA, typename TB, bool HOUT>
__device__ __forceinline__ void gemm16(
    const TA* __restrict__ A, int lda,
    const TB* __restrict__ Wt, int ldb,
    const float* __restrict__ bias, void* __restrict__ Cp, int ldc,
    int m0, int n0, int Kd, unsigned* As, unsigned* Bs)
{
    const int tid  = threadIdx.x;
    const int lane = tid & 31;
    const int warp = tid >> 5;
    const int wm = warp >> 1, wn = warp & 1;
    const int g = lane >> 2, t = lane & 3;
    const int lrow = tid >> 2, lkq = tid & 3;

    unsigned a_base = (unsigned)__cvta_generic_to_shared(As);
    unsigned b_base = (unsigned)__cvta_generic_to_shared(Bs);
    unsigned aaddr[4], baddr[2];
    {
        int mrow = ((lane >> 3) & 1) * 8 + (lane & 7);
        int ah = (lane >> 4);
        #pragma unroll
        for (int mi = 0; mi < 4; mi++)
            aaddr[mi] = a_base + ((wm * 64 + mi * 16 + mrow) * PADW + ah * 4) * 4u;
        int bh = (lane >> 3) & 1;
        int brow0 = ((lane >> 4) & 1) * 8 + (lane & 7);
        #pragma unroll
        for (int np = 0; np < 2; np++)
            baddr[np] = b_base + ((wn * 32 + np * 16 + brow0) * PADW + bh * 4) * 4u;
    }

    float acc[4][4][4] = {};
    const int nit = Kd >> 4;
    RawVec<TA> ra[4];
    RawVec<TB> rb[2];

    #pragma unroll
    for (int i = 0; i < 4; i++)
        ra[i].load(&A[(size_t)(m0 + lrow + 32 * i) * lda + lkq * 4]);
    #pragma unroll
    for (int i = 0; i < 2; i++)
        rb[i].load(&Wt[(size_t)(n0 + lrow + 32 * i) * ldb + lkq * 4]);
    #pragma unroll
    for (int i = 0; i < 4; i++)
        *reinterpret_cast<uint2*>(&As[(lrow + 32 * i) * PADW + lkq * 2]) = ra[i].pack();
    #pragma unroll
    for (int i = 0; i < 2; i++)
        *reinterpret_cast<uint2*>(&Bs[(lrow + 32 * i) * PADW + lkq * 2]) = rb[i].pack();
    __syncthreads();

    for (int it = 0; it < nit; it++) {
        const int buf = it & 1;
        const bool more = (it + 1) < nit;
        const unsigned abytes = buf * (ABUFW * 4);
        const unsigned bbytes = buf * (BBUFW * 4);

        if (more) {
            int k0 = (it + 1) << 4;
            #pragma unroll
            for (int i = 0; i < 4; i++)
                ra[i].load(&A[(size_t)(m0 + lrow + 32 * i) * lda + k0 + lkq * 4]);
            #pragma unroll
            for (int i = 0; i < 2; i++)
                rb[i].load(&Wt[(size_t)(n0 + lrow + 32 * i) * ldb + k0 + lkq * 4]);
        }

        unsigned af[4][4], bf[2][4];
        #pragma unroll
        for (int mi = 0; mi < 4; mi++) ldsm4(af[mi], aaddr[mi] + abytes);
        #pragma unroll
        for (int np = 0; np < 2; np++) ldsm4(bf[np], baddr[np] + bbytes);

        #pragma unroll
        for (int mi = 0; mi < 4; mi++)
            #pragma unroll
            for (int nj = 0; nj < 4; nj++)
                mma_f16(acc[mi][nj], af[mi], bf[nj >> 1][(nj & 1) * 2], bf[nj >> 1][(nj & 1) * 2 + 1]);

        if (more) {
            const int nb = (it + 1) & 1;
            #pragma unroll
            for (int i = 0; i < 4; i++)
                *reinterpret_cast<uint2*>(&As[nb * ABUFW + (lrow + 32 * i) * PADW + lkq * 2]) = ra[i].pack();
            #pragma unroll
            for (int i = 0; i < 2; i++)
                *reinterpret_cast<uint2*>(&Bs[nb * BBUFW + (lrow + 32 * i) * PADW + lkq * 2]) = rb[i].pack();
            __syncthreads();
        }
    }

    #pragma unroll
    for (int mi = 0; mi < 4; mi++) {
        int r = m0 + wm * 64 + mi * 16 + g;
        #pragma unroll
        for (int nj = 0; nj < 4; nj++) {
            int c = n0 + wn * 32 + nj * 8 + 2 * t;
            float b0 = bias ? bias[c] : 0.f;
            float b1 = bias ? bias[c + 1] : 0.f;
            float v0 = acc[mi][nj][0] + b0, v1 = acc[mi][nj][1] + b1;
            float v2 = acc[mi][nj][2] + b0, v3 = acc[mi][nj][3] + b1;
            if (HOUT) {
                __half* Ch = (__half*)Cp;
                *reinterpret_cast<__half2*>(&Ch[(size_t)r * ldc + c]) =
                    __float22half2_rn(make_float2(v0, v1));
                *reinterpret_cast<__half2*>(&Ch[(size_t)(r + 8) * ldc + c]) =
                    __float22half2_rn(make_float2(v2, v3));
            } else {
                float* Cf = (float*)Cp;
                *reinterpret_cast<float2*>(&Cf[(size_t)r * ldc + c]) = make_float2(v0, v1);
                *reinterpret_cast<float2*>(&Cf[(size_t)(r + 8) * ldc + c]) = make_float2(v2, v3);
            }
        }
    }
}

// qkv = x @ qkv_w^T  (fp32 in, fp16 out)
__global__ __launch_bounds__(128) void mma_qkv(
    const float* __restrict__ x, const float* __restrict__ w,
    __half* __restrict__ C)
{
    __shared__ __align__(16) unsigned As[2 * ABUFW];
    __shared__ __align__(16) unsigned Bs[2 * BBUFW];
    gemm16<float, float, true>(x, C_, w, C_, nullptr, C, QKVC,
                               blockIdx.y * BM, blockIdx.x * BN, C_, As, Bs);
}

// ---------------------------------------------------------------------------
// Single-shot K=64 G GEMM: whole K resident in smem (4 k-chunks), ONE sync,
// straight-line ldsm+mma. z = {k2, v2, k3, v3}; v slices skip OffG columns.
// ---------------------------------------------------------------------------
__global__ __launch_bounds__(128) void mma_g64(
    const __half* __restrict__ qkv, const __half* __restrict__ Wc,
    __half* __restrict__ G)
{
    const int z = blockIdx.z;
    const int n0 = blockIdx.x * BN;
    if ((z & 1) && n0 >= QKVC) return;

    __shared__ __align__(16) unsigned As[4 * ABUFW];
    __shared__ __align__(16) unsigned Bs[4 * BBUFW];

    const __half* __restrict__ A  = qkv + 256 + (z >> 1) * 64 + (z & 1) * 192;
    const __half* __restrict__ Wt = Wc + (size_t)(z >> 1) * GN * HD;
    __half* __restrict__ C = G + (size_t)z * M_ * GN;
    const int m0 = blockIdx.y * BM;

    const int tid  = threadIdx.x;
    const int lane = tid & 31;
    const int warp = tid >> 5;
    const int wm = warp >> 1, wn = warp & 1;
    const int g = lane >> 2, t = lane & 3;

    // Load A: 128 rows x 16 groups of 4 halfs (chunk = k16 block)
    #pragma unroll
    for (int i = 0; i < 16; i++) {
        int f = tid + i * 128;
        int row = f >> 4, grp = f & 15;
        int chunk = grp >> 2, kq = grp & 3;
        uint2 v = *reinterpret_cast<const uint2*>(&A[(size_t)(m0 + row) * QKVC + grp * 4]);
        *reinterpret_cast<uint2*>(&As[chunk * ABUFW + row * PADW + kq * 2]) = v;
    }
    // Load B: 64 rows x 16 groups
    #pragma unroll
    for (int i = 0; i < 8; i++) {
        int f = tid + i * 128;
        int row = f >> 4, grp = f & 15;
        int chunk = grp >> 2, kq = grp & 3;
        uint2 v = *reinterpret_cast<const uint2*>(&Wt[(size_t)(n0 + row) * HD + grp * 4]);
        *reinterpret_cast<uint2*>(&Bs[chunk * BBUFW + row * PADW + kq * 2]) = v;
    }
    __syncthreads();

    unsigned a_base = (unsigned)__cvta_generic_to_shared(As);
    unsigned b_base = (unsigned)__cvta_generic_to_shared(Bs);
    unsigned aaddr[4], baddr[2];
    {
        int mrow = ((lane >> 3) & 1) * 8 + (lane & 7);
        int ah = (lane >> 4);
        #pragma unroll
        for (int mi = 0; mi < 4; mi++)
            aaddr[mi] = a_base + ((wm * 64 + mi * 16 + mrow) * PADW + ah * 4) * 4u;
        int bh = (lane >> 3) & 1;
        int brow0 = ((lane >> 4) & 1) * 8 + (lane & 7);
        #pragma unroll
        for (int np = 0; np < 2; np++)
            baddr[np] = b_base + ((wn * 32 + np * 16 + brow0) * PADW + bh * 4) * 4u;
    }

    float acc[4][4][4] = {};
    #pragma unroll
    for (int c = 0; c < 4; c++) {
        const unsigned abytes = c * (ABUFW * 4);
        const unsigned bbytes = c * (BBUFW * 4);
        unsigned af[4][4], bf[2][4];
        #pragma unroll
        for (int mi = 0; mi < 4; mi++) ldsm4(af[mi], aaddr[mi] + abytes);
        #pragma unroll
        for (int np = 0; np < 2; np++) ldsm4(bf[np], baddr[np] + bbytes);
        #pragma unroll
        for (int mi = 0; mi < 4; mi++)
            #pragma unroll
            for (int nj = 0; nj < 4; nj++)
                mma_f16(acc[mi][nj], af[mi], bf[nj >> 1][(nj & 1) * 2], bf[nj >> 1][(nj & 1) * 2 + 1]);
    }

    #pragma unroll
    for (int mi = 0; mi < 4; mi++) {
        int r = m0 + wm * 64 + mi * 16 + g;
        #pragma unroll
        for (int nj = 0; nj < 4; nj++) {
            int c = n0 + wn * 32 + nj * 8 + 2 * t;
            *reinterpret_cast<__half2*>(&C[(size_t)r * GN + c]) =
                __float22half2_rn(make_float2(acc[mi][nj][0], acc[mi][nj][1]));
            *reinterpret_cast<__half2*>(&C[(size_t)(r + 8) * GN + c]) =
                __float22half2_rn(make_float2(acc[mi][nj][2], acc[mi][nj][3]));
        }
    }
}

// out = attn @ proj_w^T + proj_b  (fp16 A, fp32 W, fp32 out)
__global__ __launch_bounds__(128) void mma_proj(
    const __half* __restrict__ A, const float* __restrict__ w,
    const float* __restrict__ bias, float* __restrict__ out)
{
    __shared__ __align__(16) unsigned As[2 * ABUFW];
    __shared__ __align__(16) unsigned Bs[2 * BBUFW];
    gemm16<__half, float, false>(A, C_, w, C_, bias, out, C_,
                                 blockIdx.y * BM, blockIdx.x * BN, C_, As, Bs);
}

// ---------------------------------------------------------------------------
// Build combined weights (fp16)
// ---------------------------------------------------------------------------
__global__ void build_w(const float* __restrict__ dw2, const float* __restrict__ ow2,
                        const float* __restrict__ dw3, const float* __restrict__ ow3,
                        __half* __restrict__ Wc)
{
    int i = blockIdx.x * blockDim.x + threadIdx.x;
    if (i >= 2 * GN * HD) return;
    int br = i / (GN * HD);
    int r  = (i / HD) % GN;
    int c  = i % HD;
    const float* dw = br ? dw3 : dw2;
    const float* ow = br ? ow3 : ow2;
    float v = 0.f;
    if (r < QKVC) {
        int kk = r >> 6, o = r & 63;
        v = dw[o * 576 + c * 9 + kk];
    } else if (r < QKVC + 162) {
        int rr = r - QKVC, kk = rr / 18, o = rr % 18;
        v = ow[o * 576 + c * 9 + kk];
    }
    Wc[i] = __float2half(v);
}

// ---------------------------------------------------------------------------
// Deformable gather, both branches (blockIdx.y). One warp per position.
// ---------------------------------------------------------------------------
__global__ __launch_bounds__(256) void deform_gather(
    const __half* __restrict__ G,
    const float* __restrict__ ob2, const float* __restrict__ db2,
    const float* __restrict__ ob3, const float* __restrict__ db3,
    __half* __restrict__ dk2, __half* __restrict__ dv2,
    __half* __restrict__ dk3, __half* __restrict__ dv3)
{
    const int br  = blockIdx.y;
    const int dil = br + 2;
    const __half* __restrict__ Gk = G + (size_t)(2 * br) * M_ * GN;
    const __half* __restrict__ Gv = G + (size_t)(2 * br + 1) * M_ * GN;
    const float* offb = br ? ob3 : ob2;
    const float* defb = br ? db3 : db2;
    __half* dk = br ? dk3 : dk2;
    __half* dv = br ? dv3 : dv2;

    const int warp = threadIdx.x >> 5, lane = threadIdx.x & 31;
    const int pos = (blockIdx.x << 3) + warp;
    const int b = pos >> 12, hw = pos & 4095, h = hw >> 6, x = hw & 63;
    const int rbase = b << 12;

    // Phase 1: offsets (18 channels on lanes 0..17)
    float offa = (lane < 18) ? offb[lane] : 0.f;
    #pragma unroll
    for (int kq = 0; kq < 9; kq++) {
        int y  = h + (kq / 3 - 1) * dil;
        int xx = x + (kq % 3 - 1) * dil;
        if (lane < 18 && y >= 0 && y < H_ && xx >= 0 && xx < W_)
            offa += __half2float(Gk[(size_t)(rbase + (y << 6) + xx) * GN + QKVC + kq * 18 + lane]);
    }

    // Phase 2: per-tap bilinear setup (lanes 0..8 meaningful)
    int kk = lane;
    float offy = __shfl_sync(0xffffffffu, offa, (2 * lane) & 31);
    float offx = __shfl_sync(0xffffffffu, offa, (2 * lane + 1) & 31);
    float py = (float)h + (float)((kk / 3) * dil - dil) + offy;
    float px = (float)x + (float)((kk % 3) * dil - dil) + offx;
    float y0f = floorf(py), x0f = floorf(px);
    float wy = py - y0f, wx = px - x0f;
    int y0 = (int)y0f, x0 = (int)x0f, y1 = y0 + 1, x1 = x0 + 1;
    float fy0 = (float)(y0 >= 0 && y0 < H_);
    float fy1 = (float)(y1 >= 0 && y1 < H_);
    float fx0 = (float)(x0 >= 0 && x0 < W_);
    float fx1 = (float)(x1 >= 0 && x1 < W_);
    float w00 = (1.f - wy) * (1.f - wx) * fy0 * fx0;
    float w01 = (1.f - wy) * wx        * fy0 * fx1;
    float w10 = wy * (1.f - wx)        * fy1 * fx0;
    float w11 = wy * wx                * fy1 * fx1;
    int y0c = min(max(y0, 0), H_ - 1), y1c = min(max(y1, 0), H_ - 1);
    int x0c = min(max(x0, 0), W_ - 1), x1c = min(max(x1, 0), W_ - 1);
    int tapofs = kk * 64;
    int i00 = (rbase + (y0c << 6) + x0c) * GN + tapofs;
    int i01 = (rbase + (y0c << 6) + x1c) * GN + tapofs;
    int i10 = (rbase + (y1c << 6) + x0c) * GN + tapofs;
    int i11 = (rbase + (y1c << 6) + x1c) * GN + tapofs;

    const int arr = lane >> 4;            // 0 = k, 1 = v
    const int c4 = (lane & 15) * 4;
    const __half* __restrict__ Gs = arr ? Gv : Gk;

    float4 acc = *reinterpret_cast<const float4*>(&defb[c4]);

    #pragma unroll
    for (int tp = 0; tp < 9; tp++) {
        float a00 = __shfl_sync(0xffffffffu, w00, tp);
        float a01 = __shfl_sync(0xffffffffu, w01, tp);
        float a10 = __shfl_sync(0xffffffffu, w10, tp);
        float a11 = __shfl_sync(0xffffffffu, w11, tp);
        int   j00 = __shfl_sync(0xffffffffu, i00, tp);
        int   j01 = __shfl_sync(0xffffffffu, i01, tp);
        int   j10 = __shfl_sync(0xffffffffu, i10, tp);
        int   j11 = __shfl_sync(0xffffffffu, i11, tp);
        uint2 raw;
        __half2 p0, p1;
        raw = *reinterpret_cast<const uint2*>(&Gs[j00 + c4]);
        p0 = *reinterpret_cast<__half2*>(&raw.x); p1 = *reinterpret_cast<__half2*>(&raw.y);
        { float2 lo = __half22float2(p0), hi = __half22float2(p1);
          acc.x += a00 * lo.x; acc.y += a00 * lo.y; acc.z += a00 * hi.x; acc.w += a00 * hi.y; }
        raw = *reinterpret_cast<const uint2*>(&Gs[j01 + c4]);
        p0 = *reinterpret_cast<__half2*>(&raw.x); p1 = *reinterpret_cast<__half2*>(&raw.y);
        { float2 lo = __half22float2(p0), hi = __half22float2(p1);
          acc.x += a01 * lo.x; acc.y += a01 * lo.y; acc.z += a01 * hi.x; acc.w += a01 * hi.y; }
        raw = *reinterpret_cast<const uint2*>(&Gs[j10 + c4]);
        p0 = *reinterpret_cast<__half2*>(&raw.x); p1 = *reinterpret_cast<__half2*>(&raw.y);
        { float2 lo = __half22float2(p0), hi = __half22float2(p1);
          acc.x += a10 * lo.x; acc.y += a10 * lo.y; acc.z += a10 * hi.x; acc.w += a10 * hi.y; }
        raw = *reinterpret_cast<const uint2*>(&Gs[j11 + c4]);
        p0 = *reinterpret_cast<__half2*>(&raw.x); p1 = *reinterpret_cast<__half2*>(&raw.y);
        { float2 lo = __half22float2(p0), hi = __half22float2(p1);
          acc.x += a11 * lo.x; acc.y += a11 * lo.y; acc.z += a11 * hi.x; acc.w += a11 * hi.y; }
    }

    uint2 st;
    __half2 s01 = __float22half2_rn(make_float2(acc.x, acc.y));
    __half2 s23 = __float22half2_rn(make_float2(acc.z, acc.w));
    st.x = *reinterpret_cast<unsigned*>(&s01);
    st.y = *reinterpret_cast<unsigned*>(&s23);
    __half* __restrict__ dst = arr ? dv : dk;
    *reinterpret_cast<uint2*>(&dst[pos * HD + c4]) = st;
}

// ---------------------------------------------------------------------------
// 9-tap local attention, all 3 branches (blockIdx.y). Warp per position.
// Lane holds channels (2*lane, 2*lane+1).
// ---------------------------------------------------------------------------
__global__ __launch_bounds__(256) void attn_all(
    const __half* __restrict__ qkv,
    const __half* __restrict__ dk2, const __half* __restrict__ dv2,
    const __half* __restrict__ dk3, const __half* __restrict__ dv3,
    __half* __restrict__ ob)
{
    const int br = blockIdx.y;
    const int warp = threadIdx.x >> 5, lane = threadIdx.x & 31;
    const int pos = (blockIdx.x << 3) + warp;
    const int b = pos >> 12, hw = pos & 4095, h = hw >> 6, x = hw & 63;

    const __half* kb; const __half* vb; int kstride, kofs, vofs, dil;
    if (br == 0)      { kb = qkv; vb = qkv; kstride = QKVC; kofs = 192; vofs = 384; dil = 1; }
    else if (br == 1) { kb = dk2; vb = dv2; kstride = HD;   kofs = 0;   vofs = 0;   dil = 2; }
    else              { kb = dk3; vb = dv3; kstride = HD;   kofs = 0;   vofs = 0;   dil = 3; }

    const int qofs = br * 64;
    float2 q = __half22float2(*reinterpret_cast<const __half2*>(&qkv[pos * QKVC + qofs + 2 * lane]));

    float logits[9];
    #pragma unroll
    for (int kk = 0; kk < 9; kk++) {
        int y = h + (kk / 3 - 1) * dil;
        int xx = x + (kk % 3 - 1) * dil;
        float p = 0.f;
        if (y >= 0 && y < H_ && xx >= 0 && xx < W_) {
            const __half* kp = kb + ((b << 12) + (y << 6) + xx) * kstride + kofs;
            float2 kv = __half22float2(*reinterpret_cast<const __half2*>(&kp[2 * lane]));
            p = q.x * kv.x + q.y * kv.y;
        }
        #pragma unroll
        for (int s = 16; s; s >>= 1) p += __shfl_xor_sync(0xffffffffu, p, s);
        logits[kk] = p * 0.125f;
    }

    float mx = logits[0];
    #pragma unroll
    for (int kk = 1; kk < 9; kk++) mx = fmaxf(mx, logits[kk]);
    float e[9], den = 0.f;
    #pragma unroll
    for (int kk = 0; kk < 9; kk++) { e[kk] = __expf(logits[kk] - mx); den += e[kk]; }
    float inv = 1.f / den;

    float o0 = 0.f, o1 = 0.f;
    #pragma unroll
    for (int kk = 0; kk < 9; kk++) {
        int y = h + (kk / 3 - 1) * dil;
        int xx = x + (kk % 3 - 1) * dil;
        if (y >= 0 && y < H_ && xx >= 0 && xx < W_) {
            const __half* vp = vb + ((b << 12) + (y << 6) + xx) * kstride + vofs;
            float2 vv = __half22float2(*reinterpret_cast<const __half2*>(&vp[2 * lane]));
            float a = e[kk] * inv;
            o0 += a * vv.x;
            o1 += a * vv.y;
        }
    }
    *reinterpret_cast<__half2*>(&ob[pos * C_ + qofs + 2 * lane]) =
        __float22half2_rn(make_float2(o0, o1));
}

// ---------------------------------------------------------------------------
// Launch
// ---------------------------------------------------------------------------
extern "C" void kernel_launch(void* const* d_in, const int* in_sizes, int n_in,
                              void* d_out, int out_size)
{
    const float* x      = (const float*)d_in[0];
    const float* qkv_w  = (const float*)d_in[1];
    const float* proj_w = (const float*)d_in[2];
    const float* proj_b = (const float*)d_in[3];
    const float* off_w2 = (const float*)d_in[4];
    const float* off_b2 = (const float*)d_in[5];
    const float* def_w2 = (const float*)d_in[6];
    const float* def_b2 = (const float*)d_in[7];
    const float* off_w3 = (const float*)d_in[8];
    const float* off_b3 = (const float*)d_in[9];
    const float* def_w3 = (const float*)d_in[10];
    const float* def_b3 = (const float*)d_in[11];
    float* out = (float*)d_out;

    __half *p_qkv, *p_G, *p_dk2, *p_dv2, *p_dk3, *p_dv3, *p_attn, *p_wc;
    cudaGetSymbolAddress((void**)&p_qkv,  g_qkv);
    cudaGetSymbolAddress((void**)&p_G,    g_G);
    cudaGetSymbolAddress((void**)&p_dk2,  g_dk2);
    cudaGetSymbolAddress((void**)&p_dv2,  g_dv2);
    cudaGetSymbolAddress((void**)&p_dk3,  g_dk3);
    cudaGetSymbolAddress((void**)&p_dv3,  g_dv3);
    cudaGetSymbolAddress((void**)&p_attn, g_attn);
    cudaGetSymbolAddress((void**)&p_wc,   g_Wc);

    // 0) combined deform/offset weights (fp16)
    build_w<<<(2 * GN * HD + 255) / 256, 256>>>(def_w2, off_w2, def_w3, off_w3, p_wc);

    // 1) qkv = x @ qkv_w^T  -> fp16
    mma_qkv<<<dim3(QKVC / BN, M_ / BM), 128>>>(x, qkv_w, p_qkv);

    // 2) all four G projections (single-shot K=64 GEMM)
    mma_g64<<<dim3(GN / BN, M_ / BM, 4), 128>>>(p_qkv, p_wc, p_G);

    // 3) deformable gather, both branches
    deform_gather<<<dim3(M_ / 8, 2), 256>>>(p_G, off_b2, def_b2, off_b3, def_b3,
                                            p_dk2, p_dv2, p_dk3, p_dv3);

    // 4) attention, all branches -> fp16 attn
    attn_all<<<dim3(M_ / 8, 3), 256>>>(p_qkv, p_dk2, p_dv2, p_dk3, p_dv3, p_attn);

    // 5) out = attn @ proj_w^T + proj_b  (fp32 out)
    mma_proj<<<dim3(C_ / BN, M_ / BM), 128>>>(p_attn, proj_w, proj_b, out);
}

// round 15
// speedup vs baseline: 1.0972x; 1.0420x over previous
#include <cuda_runtime.h>
#include <cuda_fp16.h>
#include <math.h>

#define B_   8
#define H_   64
#define W_   64
#define M_   32768
#define C_   192
#define QKVC 576
#define HD   64
#define GN   768   // G row stride: 576 (Gk/Gv) + 162 (OffG) + pad

// ---------------------------------------------------------------------------
// Scratch (static device globals) — fp16 end-to-end intermediates
// ---------------------------------------------------------------------------
__device__ __half g_qkv[M_ * QKVC];      // [pos][576]
__device__ __half g_G[4][M_ * GN];       // z = {k2, v2, k3, v3}
__device__ __half g_dk2[M_ * HD];
__device__ __half g_dv2[M_ * HD];
__device__ __half g_dk3[M_ * HD];
__device__ __half g_dv3[M_ * HD];
__device__ __half g_attn[M_ * C_];       // [pos][branch*64+c]
__device__ __half g_Wc[2][GN * HD];      // combined [def | off] weights per branch

// ---------------------------------------------------------------------------
// fp16 MMA helpers
// ---------------------------------------------------------------------------
__device__ __forceinline__ void mma_f16(float (&d)[4], const unsigned (&a)[4],
                                        const unsigned b0, const unsigned b1) {
    asm volatile(
        "mma.sync.aligned.m16n8k16.row.col.f32.f16.f16.f32 "
        "{%0,%1,%2,%3}, {%4,%5,%6,%7}, {%8,%9}, {%0,%1,%2,%3};\n"
        : "+f"(d[0]), "+f"(d[1]), "+f"(d[2]), "+f"(d[3])
        : "r"(a[0]), "r"(a[1]), "r"(a[2]), "r"(a[3]), "r"(b0), "r"(b1));
}

__device__ __forceinline__ void ldsm4(unsigned (&r)[4], unsigned addr) {
    asm volatile("ldmatrix.sync.aligned.m8n8.x4.shared.b16 {%0,%1,%2,%3}, [%4];"
                 : "=r"(r[0]), "=r"(r[1]), "=r"(r[2]), "=r"(r[3]) : "r"(addr));
}

__device__ __forceinline__ uint2 pack_h4(float4 f) {
    __half2 h01 = __float22half2_rn(make_float2(f.x, f.y));
    __half2 h23 = __float22half2_rn(make_float2(f.z, f.w));
    uint2 v;
    v.x = *reinterpret_cast<unsigned*>(&h01);
    v.y = *reinterpret_cast<unsigned*>(&h23);
    return v;
}

template<typename T> struct RawVec;
template<> struct RawVec<float> {
    float4 v;
    __device__ __forceinline__ void load(const float* p) { v = *reinterpret_cast<const float4*>(p); }
    __device__ __forceinline__ uint2 pack() const { return pack_h4(v); }
};
template<> struct RawVec<__half> {
    uint2 v;
    __device__ __forceinline__ void load(const __half* p) { v = *reinterpret_cast<const uint2*>(p); }
    __device__ __forceinline__ uint2 pack() const { return v; }
};

#define BM 128
#define BN 64
#define PADW 12
#define ABUFW (BM * PADW)
#define BBUFW (BN * PADW)

// ---------------------------------------------------------------------------
// ldmatrix address setup (shared by all GEMM kernels)
// ---------------------------------------------------------------------------
__device__ __forceinline__ void make_ldsm_addrs(
    const unsigned* As, const unsigned* Bs, int wm, int wn, int lane,
    unsigned (&aaddr)[4], unsigned (&baddr)[2])
{
    unsigned a_base = (unsigned)__cvta_generic_to_shared(As);
    unsigned b_base = (unsigned)__cvta_generic_to_shared(Bs);
    int mrow = ((lane >> 3) & 1) * 8 + (lane & 7);
    int ah = (lane >> 4);
    #pragma unroll
    for (int mi = 0; mi < 4; mi++)
        aaddr[mi] = a_base + ((wm * 64 + mi * 16 + mrow) * PADW + ah * 4) * 4u;
    int bh = (lane >> 3) & 1;
    int brow0 = ((lane >> 4) & 1) * 8 + (lane & 7);
    #pragma unroll
    for (int np = 0; np < 2; np++)
        baddr[np] = b_base + ((wn * 32 + np * 16 + brow0) * PADW + bh * 4) * 4u;
}

// One k16 round: 6 ldsm + 16 mma, chunk at byte offsets (abytes, bbytes)
__device__ __forceinline__ void round16(
    float (&acc)[4][4][4], const unsigned (&aaddr)[4], const unsigned (&baddr)[2],
    unsigned abytes, unsigned bbytes)
{
    unsigned af[4][4], bf[2][4];
    #pragma unroll
    for (int mi = 0; mi < 4; mi++) ldsm4(af[mi], aaddr[mi] + abytes);
    #pragma unroll
    for (int np = 0; np < 2; np++) ldsm4(bf[np], baddr[np] + bbytes);
    #pragma unroll
    for (int mi = 0; mi < 4; mi++)
        #pragma unroll
        for (int nj = 0; nj < 4; nj++)
            mma_f16(acc[mi][nj], af[mi], bf[nj >> 1][(nj & 1) * 2], bf[nj >> 1][(nj & 1) * 2 + 1]);
}

// ---------------------------------------------------------------------------
// Generic double-buffered fp16 GEMM core (used by proj only now)
// ---------------------------------------------------------------------------
template<typename TA, typename TB, bool HOUT>
__device__ __forceinline__ void gemm16(
    const TA* __restrict__ A, int lda,
    const TB* __restrict__ Wt, int ldb,
    const float* __restrict__ bias, void* __restrict__ Cp, int ldc,
    int m0, int n0, int Kd, unsigned* As, unsigned* Bs)
{
    const int tid  = threadIdx.x;
    const int lane = tid & 31;
    const int warp = tid >> 5;
    const int wm = warp >> 1, wn = warp & 1;
    const int g = lane >> 2, t = lane & 3;
    const int lrow = tid >> 2, lkq = tid & 3;

    unsigned aaddr[4], baddr[2];
    make_ldsm_addrs(As, Bs, wm, wn, lane, aaddr, baddr);

    float acc[4][4][4] = {};
    const int nit = Kd >> 4;
    RawVec<TA> ra[4];
    RawVec<TB> rb[2];

    #pragma unroll
    for (int i = 0; i < 4; i++)
        ra[i].load(&A[(size_t)(m0 + lrow + 32 * i) * lda + lkq * 4]);
    #pragma unroll
    for (int i = 0; i < 2; i++)
        rb[i].load(&Wt[(size_t)(n0 + lrow + 32 * i) * ldb + lkq * 4]);
    #pragma unroll
    for (int i = 0; i < 4; i++)
        *reinterpret_cast<uint2*>(&As[(lrow + 32 * i) * PADW + lkq * 2]) = ra[i].pack();
    #pragma unroll
    for (int i = 0; i < 2; i++)
        *reinterpret_cast<uint2*>(&Bs[(lrow + 32 * i) * PADW + lkq * 2]) = rb[i].pack();
    __syncthreads();

    for (int it = 0; it < nit; it++) {
        const int buf = it & 1;
        const bool more = (it + 1) < nit;
        if (more) {
            int k0 = (it + 1) << 4;
            #pragma unroll
            for (int i = 0; i < 4; i++)
                ra[i].load(&A[(size_t)(m0 + lrow + 32 * i) * lda + k0 + lkq * 4]);
            #pragma unroll
            for (int i = 0; i < 2; i++)
                rb[i].load(&Wt[(size_t)(n0 + lrow + 32 * i) * ldb + k0 + lkq * 4]);
        }

        round16(acc, aaddr, baddr, buf * (ABUFW * 4), buf * (BBUFW * 4));

        if (more) {
            const int nb = (it + 1) & 1;
            #pragma unroll
            for (int i = 0; i < 4; i++)
                *reinterpret_cast<uint2*>(&As[nb * ABUFW + (lrow + 32 * i) * PADW + lkq * 2]) = ra[i].pack();
            #pragma unroll
            for (int i = 0; i < 2; i++)
                *reinterpret_cast<uint2*>(&Bs[nb * BBUFW + (lrow + 32 * i) * PADW + lkq * 2]) = rb[i].pack();
            __syncthreads();
        }
    }

    #pragma unroll
    for (int mi = 0; mi < 4; mi++) {
        int r = m0 + wm * 64 + mi * 16 + g;
        #pragma unroll
        for (int nj = 0; nj < 4; nj++) {
            int c = n0 + wn * 32 + nj * 8 + 2 * t;
            float b0 = bias ? bias[c] : 0.f;
            float b1 = bias ? bias[c + 1] : 0.f;
            float v0 = acc[mi][nj][0] + b0, v1 = acc[mi][nj][1] + b1;
            float v2 = acc[mi][nj][2] + b0, v3 = acc[mi][nj][3] + b1;
            if (HOUT) {
                __half* Ch = (__half*)Cp;
                *reinterpret_cast<__half2*>(&Ch[(size_t)r * ldc + c]) =
                    __float22half2_rn(make_float2(v0, v1));
                *reinterpret_cast<__half2*>(&Ch[(size_t)(r + 8) * ldc + c]) =
                    __float22half2_rn(make_float2(v2, v3));
            } else {
                float* Cf = (float*)Cp;
                *reinterpret_cast<float2*>(&Cf[(size_t)r * ldc + c]) = make_float2(v0, v1);
                *reinterpret_cast<float2*>(&Cf[(size_t)(r + 8) * ldc + c]) = make_float2(v2, v3);
            }
        }
    }
}

// ---------------------------------------------------------------------------
// Persistent-n qkv GEMM: A (128x192 fp32->fp16) resident in smem (12 chunks),
// loop over 3 n-tiles reloading only B. grid (3, 256).
// ---------------------------------------------------------------------------
#define QKC 12   // K/16 for K=192
__global__ __launch_bounds__(128) void mma_qkv_p(
    const float* __restrict__ x, const float* __restrict__ w,
    __half* __restrict__ C)
{
    extern __shared__ __align__(16) unsigned sm[];
    unsigned* As = sm;                   // QKC * ABUFW
    unsigned* Bs = sm + QKC * ABUFW;     // QKC * BBUFW

    const int tid  = threadIdx.x;
    const int lane = tid & 31;
    const int warp = tid >> 5;
    const int wm = warp >> 1, wn = warp & 1;
    const int g = lane >> 2, t = lane & 3;
    const int m0 = blockIdx.y * BM;

    // A: 128 rows x 48 groups of 4 floats
    #pragma unroll
    for (int i = 0; i < 48; i++) {
        int f = tid + i * 128;
        int row = f / 48, grp = f % 48;
        int ch = grp >> 2, kq = grp & 3;
        float4 v = *reinterpret_cast<const float4*>(&x[(size_t)(m0 + row) * C_ + grp * 4]);
        *reinterpret_cast<uint2*>(&As[ch * ABUFW + row * PADW + kq * 2]) = pack_h4(v);
    }

    unsigned aaddr[4], baddr[2];
    make_ldsm_addrs(As, Bs, wm, wn, lane, aaddr, baddr);

    for (int tt = 0; tt < 3; tt++) {
        const int n0 = (blockIdx.x * 3 + tt) * BN;
        __syncthreads();     // A visible (tt=0) / prior compute done with Bs
        #pragma unroll
        for (int i = 0; i < 24; i++) {
            int f = tid + i * 128;
            int row = f / 48, grp = f % 48;
            int ch = grp >> 2, kq = grp & 3;
            float4 v = *reinterpret_cast<const float4*>(&w[(size_t)(n0 + row) * C_ + grp * 4]);
            *reinterpret_cast<uint2*>(&Bs[ch * BBUFW + row * PADW + kq * 2]) = pack_h4(v);
        }
        __syncthreads();

        float acc[4][4][4] = {};
        #pragma unroll
        for (int ch = 0; ch < QKC; ch++)
            round16(acc, aaddr, baddr, ch * (ABUFW * 4), ch * (BBUFW * 4));

        #pragma unroll
        for (int mi = 0; mi < 4; mi++) {
            int r = m0 + wm * 64 + mi * 16 + g;
            #pragma unroll
            for (int nj = 0; nj < 4; nj++) {
                int c = n0 + wn * 32 + nj * 8 + 2 * t;
                *reinterpret_cast<__half2*>(&C[(size_t)r * QKVC + c]) =
                    __float22half2_rn(make_float2(acc[mi][nj][0], acc[mi][nj][1]));
                *reinterpret_cast<__half2*>(&C[(size_t)(r + 8) * QKVC + c]) =
                    __float22half2_rn(make_float2(acc[mi][nj][2], acc[mi][nj][3]));
            }
        }
    }
}

// ---------------------------------------------------------------------------
// Persistent-n G GEMM: A (128x64) resident, loop 6 n-tiles per block.
// grid (2, 256, 4). v slices (z odd) clamp to 9 n-tiles (skip OffG).
// ---------------------------------------------------------------------------
__global__ __launch_bounds__(128) void mma_g64p(
    const __half* __restrict__ qkv, const __half* __restrict__ Wc,
    __half* __restrict__ G)
{
    const int z = blockIdx.z;
    __shared__ __align__(16) unsigned As[4 * ABUFW];
    __shared__ __align__(16) unsigned Bs[4 * BBUFW];

    const __half* __restrict__ A  = qkv + 256 + (z >> 1) * 64 + (z & 1) * 192;
    const __half* __restrict__ Wt = Wc + (size_t)(z >> 1) * GN * HD;
    __half* __restrict__ C = G + (size_t)z * M_ * GN;
    const int m0 = blockIdx.y * BM;

    const int tid  = threadIdx.x;
    const int lane = tid & 31;
    const int warp = tid >> 5;
    const int wm = warp >> 1, wn = warp & 1;
    const int g = lane >> 2, t = lane & 3;

    // A: 128 rows x 16 groups
    #pragma unroll
    for (int i = 0; i < 16; i++) {
        int f = tid + i * 128;
        int row = f >> 4, grp = f & 15;
        int ch = grp >> 2, kq = grp & 3;
        uint2 v = *reinterpret_cast<const uint2*>(&A[(size_t)(m0 + row) * QKVC + grp * 4]);
        *reinterpret_cast<uint2*>(&As[ch * ABUFW + row * PADW + kq * 2]) = v;
    }

    unsigned aaddr[4], baddr[2];
    make_ldsm_addrs(As, Bs, wm, wn, lane, aaddr, baddr);

    const int tend = (z & 1) ? 9 : 12;
    const int t0 = blockIdx.x * 6;
    const int t1 = min(t0 + 6, tend);

    for (int tt = t0; tt < t1; tt++) {
        const int n0 = tt * BN;
        __syncthreads();
        #pragma unroll
        for (int i = 0; i < 8; i++) {
            int f = tid + i * 128;
            int row = f >> 4, grp = f & 15;
            int ch = grp >> 2, kq = grp & 3;
            uint2 v = *reinterpret_cast<const uint2*>(&Wt[(size_t)(n0 + row) * HD + grp * 4]);
            *reinterpret_cast<uint2*>(&Bs[ch * BBUFW + row * PADW + kq * 2]) = v;
        }
        __syncthreads();

        float acc[4][4][4] = {};
        #pragma unroll
        for (int ch = 0; ch < 4; ch++)
            round16(acc, aaddr, baddr, ch * (ABUFW * 4), ch * (BBUFW * 4));

        #pragma unroll
        for (int mi = 0; mi < 4; mi++) {
            int r = m0 + wm * 64 + mi * 16 + g;
            #pragma unroll
            for (int nj = 0; nj < 4; nj++) {
                int c = n0 + wn * 32 + nj * 8 + 2 * t;
                *reinterpret_cast<__half2*>(&C[(size_t)r * GN + c]) =
                    __float22half2_rn(make_float2(acc[mi][nj][0], acc[mi][nj][1]));
                *reinterpret_cast<__half2*>(&C[(size_t)(r + 8) * GN + c]) =
                    __float22half2_rn(make_float2(acc[mi][nj][2], acc[mi][nj][3]));
            }
        }
    }
}

// out = attn @ proj_w^T + proj_b  (fp16 A, fp32 W, fp32 out)
__global__ __launch_bounds__(128) void mma_proj(
    const __half* __restrict__ A, const float* __restrict__ w,
    const float* __restrict__ bias, float* __restrict__ out)
{
    __shared__ __align__(16) unsigned As[2 * ABUFW];
    __shared__ __align__(16) unsigned Bs[2 * BBUFW];
    gemm16<__half, float, false>(A, C_, w, C_, bias, out, C_,
                                 blockIdx.y * BM, blockIdx.x * BN, C_, As, Bs);
}

// ---------------------------------------------------------------------------
// Build combined weights (fp16)
// ---------------------------------------------------------------------------
__global__ void build_w(const float* __restrict__ dw2, const float* __restrict__ ow2,
                        const float* __restrict__ dw3, const float* __restrict__ ow3,
                        __half* __restrict__ Wc)
{
    int i = blockIdx.x * blockDim.x + threadIdx.x;
    if (i >= 2 * GN * HD) return;
    int br = i / (GN * HD);
    int r  = (i / HD) % GN;
    int c  = i % HD;
    const float* dw = br ? dw3 : dw2;
    const float* ow = br ? ow3 : ow2;
    float v = 0.f;
    if (r < QKVC) {
        int kk = r >> 6, o = r & 63;
        v = dw[o * 576 + c * 9 + kk];
    } else if (r < QKVC + 162) {
        int rr = r - QKVC, kk = rr / 18, o = rr % 18;
        v = ow[o * 576 + c * 9 + kk];
    }
    Wc[i] = __float2half(v);
}

// ---------------------------------------------------------------------------
// Deformable gather, both branches (blockIdx.y). One warp per position.
// ---------------------------------------------------------------------------
__global__ __launch_bounds__(256) void deform_gather(
    const __half* __restrict__ G,
    const float* __restrict__ ob2, const float* __restrict__ db2,
    const float* __restrict__ ob3, const float* __restrict__ db3,
    __half* __restrict__ dk2, __half* __restrict__ dv2,
    __half* __restrict__ dk3, __half* __restrict__ dv3)
{
    const int br  = blockIdx.y;
    const int dil = br + 2;
    const __half* __restrict__ Gk = G + (size_t)(2 * br) * M_ * GN;
    const __half* __restrict__ Gv = G + (size_t)(2 * br + 1) * M_ * GN;
    const float* offb = br ? ob3 : ob2;
    const float* defb = br ? db3 : db2;
    __half* dk = br ? dk3 : dk2;
    __half* dv = br ? dv3 : dv2;

    const int warp = threadIdx.x >> 5, lane = threadIdx.x & 31;
    const int pos = (blockIdx.x << 3) + warp;
    const int b = pos >> 12, hw = pos & 4095, h = hw >> 6, x = hw & 63;
    const int rbase = b << 12;

    // Phase 1: offsets (18 channels on lanes 0..17)
    float offa = (lane < 18) ? offb[lane] : 0.f;
    #pragma unroll
    for (int kq = 0; kq < 9; kq++) {
        int y  = h + (kq / 3 - 1) * dil;
        int xx = x + (kq % 3 - 1) * dil;
        if (lane < 18 && y >= 0 && y < H_ && xx >= 0 && xx < W_)
            offa += __half2float(Gk[(size_t)(rbase + (y << 6) + xx) * GN + QKVC + kq * 18 + lane]);
    }

    // Phase 2: per-tap bilinear setup (lanes 0..8 meaningful)
    int kk = lane;
    float offy = __shfl_sync(0xffffffffu, offa, (2 * lane) & 31);
    float offx = __shfl_sync(0xffffffffu, offa, (2 * lane + 1) & 31);
    float py = (float)h + (float)((kk / 3) * dil - dil) + offy;
    float px = (float)x + (float)((kk % 3) * dil - dil) + offx;
    float y0f = floorf(py), x0f = floorf(px);
    float wy = py - y0f, wx = px - x0f;
    int y0 = (int)y0f, x0 = (int)x0f, y1 = y0 + 1, x1 = x0 + 1;
    float fy0 = (float)(y0 >= 0 && y0 < H_);
    float fy1 = (float)(y1 >= 0 && y1 < H_);
    float fx0 = (float)(x0 >= 0 && x0 < W_);
    float fx1 = (float)(x1 >= 0 && x1 < W_);
    float w00 = (1.f - wy) * (1.f - wx) * fy0 * fx0;
    float w01 = (1.f - wy) * wx        * fy0 * fx1;
    float w10 = wy * (1.f - wx)        * fy1 * fx0;
    float w11 = wy * wx                * fy1 * fx1;
    int y0c = min(max(y0, 0), H_ - 1), y1c = min(max(y1, 0), H_ - 1);
    int x0c = min(max(x0, 0), W_ - 1), x1c = min(max(x1, 0), W_ - 1);
    int tapofs = kk * 64;
    int i00 = (rbase + (y0c << 6) + x0c) * GN + tapofs;
    int i01 = (rbase + (y0c << 6) + x1c) * GN + tapofs;
    int i10 = (rbase + (y1c << 6) + x0c) * GN + tapofs;
    int i11 = (rbase + (y1c << 6) + x1c) * GN + tapofs;

    const int arr = lane >> 4;            // 0 = k, 1 = v
    const int c4 = (lane & 15) * 4;
    const __half* __restrict__ Gs = arr ? Gv : Gk;

    float4 acc = *reinterpret_cast<const float4*>(&defb[c4]);

    #pragma unroll
    for (int tp = 0; tp < 9; tp++) {
        float a00 = __shfl_sync(0xffffffffu, w00, tp);
        float a01 = __shfl_sync(0xffffffffu, w01, tp);
        float a10 = __shfl_sync(0xffffffffu, w10, tp);
        float a11 = __shfl_sync(0xffffffffu, w11, tp);
        int   j00 = __shfl_sync(0xffffffffu, i00, tp);
        int   j01 = __shfl_sync(0xffffffffu, i01, tp);
        int   j10 = __shfl_sync(0xffffffffu, i10, tp);
        int   j11 = __shfl_sync(0xffffffffu, i11, tp);
        uint2 raw;
        __half2 p0, p1;
        raw = *reinterpret_cast<const uint2*>(&Gs[j00 + c4]);
        p0 = *reinterpret_cast<__half2*>(&raw.x); p1 = *reinterpret_cast<__half2*>(&raw.y);
        { float2 lo = __half22float2(p0), hi = __half22float2(p1);
          acc.x += a00 * lo.x; acc.y += a00 * lo.y; acc.z += a00 * hi.x; acc.w += a00 * hi.y; }
        raw = *reinterpret_cast<const uint2*>(&Gs[j01 + c4]);
        p0 = *reinterpret_cast<__half2*>(&raw.x); p1 = *reinterpret_cast<__half2*>(&raw.y);
        { float2 lo = __half22float2(p0), hi = __half22float2(p1);
          acc.x += a01 * lo.x; acc.y += a01 * lo.y; acc.z += a01 * hi.x; acc.w += a01 * hi.y; }
        raw = *reinterpret_cast<const uint2*>(&Gs[j10 + c4]);
        p0 = *reinterpret_cast<__half2*>(&raw.x); p1 = *reinterpret_cast<__half2*>(&raw.y);
        { float2 lo = __half22float2(p0), hi = __half22float2(p1);
          acc.x += a10 * lo.x; acc.y += a10 * lo.y; acc.z += a10 * hi.x; acc.w += a10 * hi.y; }
        raw = *reinterpret_cast<const uint2*>(&Gs[j11 + c4]);
        p0 = *reinterpret_cast<__half2*>(&raw.x); p1 = *reinterpret_cast<__half2*>(&raw.y);
        { float2 lo = __half22float2(p0), hi = __half22float2(p1);
          acc.x += a11 * lo.x; acc.y += a11 * lo.y; acc.z += a11 * hi.x; acc.w += a11 * hi.y; }
    }

    uint2 st;
    __half2 s01 = __float22half2_rn(make_float2(acc.x, acc.y));
    __half2 s23 = __float22half2_rn(make_float2(acc.z, acc.w));
    st.x = *reinterpret_cast<unsigned*>(&s01);
    st.y = *reinterpret_cast<unsigned*>(&s23);
    __half* __restrict__ dst = arr ? dv : dk;
    *reinterpret_cast<uint2*>(&dst[pos * HD + c4]) = st;
}

// ---------------------------------------------------------------------------
// 9-tap local attention, all 3 branches (blockIdx.y). Warp per position.
// ---------------------------------------------------------------------------
__global__ __launch_bounds__(256) void attn_all(
    const __half* __restrict__ qkv,
    const __half* __restrict__ dk2, const __half* __restrict__ dv2,
    const __half* __restrict__ dk3, const __half* __restrict__ dv3,
    __half* __restrict__ ob)
{
    const int br = blockIdx.y;
    const int warp = threadIdx.x >> 5, lane = threadIdx.x & 31;
    const int pos = (blockIdx.x << 3) + warp;
    const int b = pos >> 12, hw = pos & 4095, h = hw >> 6, x = hw & 63;

    const __half* kb; const __half* vb; int kstride, kofs, vofs, dil;
    if (br == 0)      { kb = qkv; vb = qkv; kstride = QKVC; kofs = 192; vofs = 384; dil = 1; }
    else if (br == 1) { kb = dk2; vb = dv2; kstride = HD;   kofs = 0;   vofs = 0;   dil = 2; }
    else              { kb = dk3; vb = dv3; kstride = HD;   kofs = 0;   vofs = 0;   dil = 3; }

    const int qofs = br * 64;
    float2 q = __half22float2(*reinterpret_cast<const __half2*>(&qkv[pos * QKVC + qofs + 2 * lane]));

    float logits[9];
    #pragma unroll
    for (int kk = 0; kk < 9; kk++) {
        int y = h + (kk / 3 - 1) * dil;
        int xx = x + (kk % 3 - 1) * dil;
        float p = 0.f;
        if (y >= 0 && y < H_ && xx >= 0 && xx < W_) {
            const __half* kp = kb + ((b << 12) + (y << 6) + xx) * kstride + kofs;
            float2 kv = __half22float2(*reinterpret_cast<const __half2*>(&kp[2 * lane]));
            p = q.x * kv.x + q.y * kv.y;
        }
        #pragma unroll
        for (int s = 16; s; s >>= 1) p += __shfl_xor_sync(0xffffffffu, p, s);
        logits[kk] = p * 0.125f;
    }

    float mx = logits[0];
    #pragma unroll
    for (int kk = 1; kk < 9; kk++) mx = fmaxf(mx, logits[kk]);
    float e[9], den = 0.f;
    #pragma unroll
    for (int kk = 0; kk < 9; kk++) { e[kk] = __expf(logits[kk] - mx); den += e[kk]; }
    float inv = 1.f / den;

    float o0 = 0.f, o1 = 0.f;
    #pragma unroll
    for (int kk = 0; kk < 9; kk++) {
        int y = h + (kk / 3 - 1) * dil;
        int xx = x + (kk % 3 - 1) * dil;
        if (y >= 0 && y < H_ && xx >= 0 && xx < W_) {
            const __half* vp = vb + ((b << 12) + (y << 6) + xx) * kstride + vofs;
            float2 vv = __half22float2(*reinterpret_cast<const __half2*>(&vp[2 * lane]));
            float a = e[kk] * inv;
            o0 += a * vv.x;
            o1 += a * vv.y;
        }
    }
    *reinterpret_cast<__half2*>(&ob[pos * C_ + qofs + 2 * lane]) =
        __float22half2_rn(make_float2(o0, o1));
}

// ---------------------------------------------------------------------------
// Launch
// ---------------------------------------------------------------------------
extern "C" void kernel_launch(void* const* d_in, const int* in_sizes, int n_in,
                              void* d_out, int out_size)
{
    const float* x      = (const float*)d_in[0];
    const float* qkv_w  = (const float*)d_in[1];
    const float* proj_w = (const float*)d_in[2];
    const float* proj_b = (const float*)d_in[3];
    const float* off_w2 = (const float*)d_in[4];
    const float* off_b2 = (const float*)d_in[5];
    const float* def_w2 = (const float*)d_in[6];
    const float* def_b2 = (const float*)d_in[7];
    const float* off_w3 = (const float*)d_in[8];
    const float* off_b3 = (const float*)d_in[9];
    const float* def_w3 = (const float*)d_in[10];
    const float* def_b3 = (const float*)d_in[11];
    float* out = (float*)d_out;

    __half *p_qkv, *p_G, *p_dk2, *p_dv2, *p_dk3, *p_dv3, *p_attn, *p_wc;
    cudaGetSymbolAddress((void**)&p_qkv,  g_qkv);
    cudaGetSymbolAddress((void**)&p_G,    g_G);
    cudaGetSymbolAddress((void**)&p_dk2,  g_dk2);
    cudaGetSymbolAddress((void**)&p_dv2,  g_dv2);
    cudaGetSymbolAddress((void**)&p_dk3,  g_dk3);
    cudaGetSymbolAddress((void**)&p_dv3,  g_dv3);
    cudaGetSymbolAddress((void**)&p_attn, g_attn);
    cudaGetSymbolAddress((void**)&p_wc,   g_Wc);

    // qkv persistent kernel needs >48KB dynamic smem
    static bool attr_done = false;
    const int qkv_smem = (QKC * ABUFW + QKC * BBUFW) * 4;   // 110,592 B
    if (!attr_done) {
        cudaFuncSetAttribute(mma_qkv_p, cudaFuncAttributeMaxDynamicSharedMemorySize, qkv_smem);
        attr_done = true;
    }

    // 0) combined deform/offset weights (fp16)
    build_w<<<(2 * GN * HD + 255) / 256, 256>>>(def_w2, off_w2, def_w3, off_w3, p_wc);

    // 1) qkv = x @ qkv_w^T  -> fp16  (persistent-n, A resident)
    mma_qkv_p<<<dim3(3, M_ / BM), 128, qkv_smem>>>(x, qkv_w, p_qkv);

    // 2) all four G projections (persistent-n, A resident)
    mma_g64p<<<dim3(2, M_ / BM, 4), 128>>>(p_qkv, p_wc, p_G);

    // 3) deformable gather, both branches
    deform_gather<<<dim3(M_ / 8, 2), 256>>>(p_G, off_b2, def_b2, off_b3, def_b3,
                                            p_dk2, p_dv2, p_dk3, p_dv3);

    // 4) attention, all branches -> fp16 attn
    attn_all<<<dim3(M_ / 8, 3), 256>>>(p_qkv, p_dk2, p_dv2, p_dk3, p_dv3, p_attn);

    // 5) out = attn @ proj_w^T + proj_b  (fp32 out)
    mma_proj<<<dim3(C_ / BN, M_ / BM), 128>>>(p_attn, proj_w, proj_b, out);
}